// round 12
// baseline (speedup 1.0000x reference)
#include <cuda_runtime.h>
#include <cuda_bf16.h>
#include <math.h>
#include <stdint.h>

#define N_NODES 100000
#define N_EDGES 1600000
#define D 128
#define N_LAYERS 4
#define N_GRAPHS 512
#define LN_EPS 1e-5f
#define NB_SCAN 391          // ceil(N_NODES/256); also prep grid size
#define PREP_THREADS (NB_SCAN * 256)   // 100096

// ---------------- scratch (device globals; no allocation allowed) ----------------
__device__ __align__(16) __nv_bfloat16 g_hb[N_NODES * D];   // post-GEMM feats, bf16, pre-scaled by dis
__device__ __align__(16) __nv_bfloat16 g_curb[N_NODES * D]; // layer features (bf16)
__device__ int   g_rowptr[N_NODES + 1];
__device__ int   g_cnt[N_NODES];          // in-degree, then CSR fill cursor
__device__ int   g_esrc[N_EDGES];         // edge sources grouped by dst
__device__ __align__(16) float g_dis[N_NODES];        // deg^{-1/2} (with self loop)
__device__ __align__(16) float g_pool[N_GRAPHS * D];
__device__ __align__(16) float g_pcnt[N_GRAPHS];
__device__ int g_bsum[NB_SCAN];
__device__ int g_is64_ei;
__device__ int g_is64_b;
__device__ int g_bar_count = 0;
__device__ volatile int g_bar_gen = 0;

// ---------------- helpers ----------------
__device__ __forceinline__ int load_idx(const void* p, long long i, int is64) {
    return is64 ? (int)((const long long*)p)[i] : ((const int*)p)[i];
}

__device__ __forceinline__ uint32_t to_tf32(float f) {
    uint32_t u;
    asm("cvt.rna.tf32.f32 %0, %1;" : "=r"(u) : "f"(f));
    return u;
}

__device__ __forceinline__ void mma_tf32(float* c, const uint32_t* a, const uint32_t* b) {
    asm volatile(
        "mma.sync.aligned.m16n8k8.row.col.f32.tf32.tf32.f32 "
        "{%0,%1,%2,%3}, {%4,%5,%6,%7}, {%8,%9}, {%0,%1,%2,%3};"
        : "+f"(c[0]), "+f"(c[1]), "+f"(c[2]), "+f"(c[3])
        : "r"(a[0]), "r"(a[1]), "r"(a[2]), "r"(a[3]), "r"(b[0]), "r"(b[1]));
}

__device__ __forceinline__ void acc8(float* acc, uint4 u) {
    float2 f0 = __bfloat1622float2(*(__nv_bfloat162*)&u.x);
    float2 f1 = __bfloat1622float2(*(__nv_bfloat162*)&u.y);
    float2 f2 = __bfloat1622float2(*(__nv_bfloat162*)&u.z);
    float2 f3 = __bfloat1622float2(*(__nv_bfloat162*)&u.w);
    acc[0] += f0.x; acc[1] += f0.y; acc[2] += f1.x; acc[3] += f1.y;
    acc[4] += f2.x; acc[5] += f2.y; acc[6] += f3.x; acc[7] += f3.y;
}

// Sense-reversing software grid barrier. Safe: all NB_SCAN blocks are
// co-resident (391 blocks of 256 thr on 148 SMs). Generation counter is
// monotonic across graph replays; count is reset by the releaser.
__device__ __forceinline__ void grid_barrier() {
    __syncthreads();
    if (threadIdx.x == 0) {
        __threadfence();
        int gen = g_bar_gen;
        if (atomicAdd(&g_bar_count, 1) == NB_SCAN - 1) {
            g_bar_count = 0;
            __threadfence();
            g_bar_gen = gen + 1;
        } else {
            while (g_bar_gen == gen) __nanosleep(64);
        }
        __threadfence();
    }
    __syncthreads();
}

// ---------------- 1. fused prep: zero+detect | hist | reduce | rowptr | fill ----
__global__ __launch_bounds__(256) void prep_all_kernel(const void* __restrict__ ei,
                                                       const int* __restrict__ ei32,
                                                       const int* __restrict__ b32) {
    int t = threadIdx.x, b = blockIdx.x;
    int gid = b * 256 + t;
    int lane = t & 31, wid = t >> 5;
    __shared__ int ws[8];
    __shared__ int wsum[8], woff[8];
    __shared__ int s_boff;

    // ---- phase A: zero counters + dtype detect ----
    if (gid < N_NODES) g_cnt[gid] = 0;
    if (gid < N_GRAPHS * D) g_pool[gid] = 0.f;
    if (gid < N_GRAPHS) g_pcnt[gid] = 0.f;
    if (b == 0) {
        __shared__ int cnt_e, cnt_b;
        if (t == 0) { cnt_e = 0; cnt_b = 0; }
        __syncthreads();
        const int n_e = 2 * N_EDGES, n_b = N_NODES;
        for (int k = t; k < 256; k += 256) {
            long long pe = (long long)(2 * k + 1) * n_e / 512;
            pe |= 1; if (pe >= n_e) pe = (n_e - 1) | 1;
            if (pe < n_e && ei32[pe] != 0) atomicAdd(&cnt_e, 1);
            long long pb = (long long)(2 * k + 1) * n_b / 512;
            pb |= 1; if (pb >= n_b) pb = (n_b - 1) | 1;
            if (pb < n_b && b32[pb] != 0) atomicAdd(&cnt_b, 1);
        }
        __syncthreads();
        if (t == 0) {
            g_is64_ei = (cnt_e == 0) ? 1 : 0;
            g_is64_b  = (cnt_b == 0) ? 1 : 0;
        }
    }
    grid_barrier();

    // ---- phase B: in-degree histogram (grid-stride) ----
    int is64 = g_is64_ei;
    for (long long j = gid; j < N_EDGES; j += PREP_THREADS) {
        int dst = load_idx(ei, (long long)N_EDGES + j, is64);
        atomicAdd(&g_cnt[dst], 1);
    }
    grid_barrier();

    // ---- phase C: per-block reduce -> g_bsum[b] ----
    int c = (gid < N_NODES) ? g_cnt[gid] : 0;
    {
        int s = c;
#pragma unroll
        for (int off = 16; off > 0; off >>= 1)
            s += __shfl_xor_sync(0xffffffffu, s, off);
        if (lane == 0) ws[wid] = s;
        __syncthreads();
        if (t == 0) {
            int tot = 0;
#pragma unroll
            for (int w = 0; w < 8; ++w) tot += ws[w];
            g_bsum[b] = tot;
        }
    }
    grid_barrier();

    // ---- phase E: block offset (reduction over bsum[0..b)) + in-block scan ----
    {
        int part = 0;
        for (int j = t; j < b; j += 256) part += g_bsum[j];
#pragma unroll
        for (int off = 16; off > 0; off >>= 1)
            part += __shfl_xor_sync(0xffffffffu, part, off);
        if (lane == 0) ws[wid] = part;
        __syncthreads();
        if (t == 0) {
            int tot = 0;
#pragma unroll
            for (int w = 0; w < 8; ++w) tot += ws[w];
            s_boff = tot;
        }
        __syncthreads();
    }
    {
        int incl = c;
#pragma unroll
        for (int off = 1; off < 32; off <<= 1) {
            int n = __shfl_up_sync(0xffffffffu, incl, off);
            if (lane >= off) incl += n;
        }
        if (lane == 31) wsum[wid] = incl;
        __syncthreads();
        if (wid == 0 && lane < 8) {
            int wv = wsum[lane];
            int wi = wv;
#pragma unroll
            for (int off = 1; off < 8; off <<= 1) {
                int n = __shfl_up_sync(0xffu, wi, off);
                if (lane >= off) wi += n;
            }
            woff[lane] = wi - wv;
        }
        __syncthreads();
        if (gid < N_NODES) {
            int rp = s_boff + woff[wid] + (incl - c);
            g_rowptr[gid] = rp;
            g_cnt[gid] = rp;                          // CSR fill cursor
            g_dis[gid] = rsqrtf((float)c + 1.0f);     // deg^{-1/2} with self loop
            if (gid == N_NODES - 1) g_rowptr[N_NODES] = rp + c;
        }
    }
    grid_barrier();

    // ---- phase F: CSR fill (grid-stride) ----
    for (long long j = gid; j < N_EDGES; j += PREP_THREADS) {
        int src = load_idx(ei, j, is64);
        int dst = load_idx(ei, (long long)N_EDGES + j, is64);
        int pos = atomicAdd(&g_cnt[dst], 1);
        g_esrc[pos] = src;
    }
}

// ---------------- 6. TF32 tensor-core GEMM + scaled-bf16 epilogue ----------------
// outb[v, :] = bf16( (A @ W)[v, :] * dis[v] )
// A = fp32 x (layer 0) or bf16 g_curb (layers 1+; bf16->tf32 via bit-shift).
__global__ __launch_bounds__(256) void gemm_tc_kernel(const float* __restrict__ Af,
                                                      int a_f32,
                                                      const float* __restrict__ W,
                                                      __nv_bfloat16* __restrict__ outb) {
    __shared__ uint32_t sX[128 * 36];   // stride 36 -> conflict-free A frags
    __shared__ uint32_t sW[32 * 132];   // stride 132 -> <=2-way on B frags
    int tid = threadIdx.x;
    int lane = tid & 31, wid = tid >> 5;
    int warp_m = wid >> 1, warp_n = wid & 1;
    int tg = lane >> 2, tc = lane & 3;
    int br = blockIdx.x * 128;

    float acc[2][8][4];
#pragma unroll
    for (int mt = 0; mt < 2; ++mt)
#pragma unroll
        for (int nt = 0; nt < 8; ++nt)
#pragma unroll
            for (int q = 0; q < 4; ++q) acc[mt][nt][q] = 0.f;

    for (int kc = 0; kc < 4; ++kc) {
        int k0 = kc * 32;
        if (a_f32) {
#pragma unroll
            for (int it = 0; it < 4; ++it) {
                int idx = tid + it * 256;
                int row = idx >> 3, kq = idx & 7;
                float4 v = make_float4(0.f, 0.f, 0.f, 0.f);
                if (br + row < N_NODES)
                    v = *(const float4*)&Af[(size_t)(br + row) * D + k0 + kq * 4];
                uint4 u = make_uint4(to_tf32(v.x), to_tf32(v.y), to_tf32(v.z), to_tf32(v.w));
                *(uint4*)&sX[row * 36 + kq * 4] = u;
            }
        } else {
#pragma unroll
            for (int it = 0; it < 2; ++it) {
                int idx = tid + it * 256;
                int row = idx >> 2, q = idx & 3;   // q: 16B chunk = 8 bf16
                uint4 u = make_uint4(0, 0, 0, 0);
                if (br + row < N_NODES)
                    u = *(const uint4*)&g_curb[(size_t)(br + row) * D + k0 + q * 8];
                uint4 o0 = make_uint4(u.x << 16, u.x & 0xffff0000u,
                                      u.y << 16, u.y & 0xffff0000u);
                uint4 o1 = make_uint4(u.z << 16, u.z & 0xffff0000u,
                                      u.w << 16, u.w & 0xffff0000u);
                *(uint4*)&sX[row * 36 + q * 8]     = o0;
                *(uint4*)&sX[row * 36 + q * 8 + 4] = o1;
            }
        }
#pragma unroll
        for (int it = 0; it < 4; ++it) {
            int idx = tid + it * 256;
            int k = idx >> 5, q = idx & 31;
            float4 v = *(const float4*)&W[(size_t)(k0 + k) * D + q * 4];
            uint4 u = make_uint4(to_tf32(v.x), to_tf32(v.y), to_tf32(v.z), to_tf32(v.w));
            *(uint4*)&sW[k * 132 + q * 4] = u;
        }
        __syncthreads();

#pragma unroll
        for (int kk = 0; kk < 4; ++kk) {
            uint32_t a[2][4], b[8][2];
#pragma unroll
            for (int mt = 0; mt < 2; ++mt) {
                int r0 = warp_m * 32 + mt * 16 + tg;
                a[mt][0] = sX[r0 * 36 + kk * 8 + tc];
                a[mt][1] = sX[(r0 + 8) * 36 + kk * 8 + tc];
                a[mt][2] = sX[r0 * 36 + kk * 8 + tc + 4];
                a[mt][3] = sX[(r0 + 8) * 36 + kk * 8 + tc + 4];
            }
#pragma unroll
            for (int nt = 0; nt < 8; ++nt) {
                int n0 = warp_n * 64 + nt * 8 + tg;
                b[nt][0] = sW[(kk * 8 + tc) * 132 + n0];
                b[nt][1] = sW[(kk * 8 + 4 + tc) * 132 + n0];
            }
#pragma unroll
            for (int mt = 0; mt < 2; ++mt)
#pragma unroll
                for (int nt = 0; nt < 8; ++nt)
                    mma_tf32(acc[mt][nt], a[mt], b[nt]);
        }
        __syncthreads();
    }

#pragma unroll
    for (int mt = 0; mt < 2; ++mt) {
        int r0 = br + warp_m * 32 + mt * 16 + tg;
        float ds0 = (r0 < N_NODES) ? g_dis[r0] : 0.f;
        float ds1 = (r0 + 8 < N_NODES) ? g_dis[r0 + 8] : 0.f;
#pragma unroll
        for (int nt = 0; nt < 8; ++nt) {
            int c0 = warp_n * 64 + nt * 8 + 2 * tc;
            if (r0 < N_NODES) {
                __nv_bfloat162 p = __floats2bfloat162_rn(acc[mt][nt][0] * ds0,
                                                         acc[mt][nt][1] * ds0);
                *(__nv_bfloat162*)&outb[(size_t)r0 * D + c0] = p;
            }
            if (r0 + 8 < N_NODES) {
                __nv_bfloat162 p = __floats2bfloat162_rn(acc[mt][nt][2] * ds1,
                                                         acc[mt][nt][3] * ds1);
                *(__nv_bfloat162*)&outb[(size_t)(r0 + 8) * D + c0] = p;
            }
        }
    }
}

// ---------------- 7. fused aggregation + bias + LN + residual/relu (+pool) -------
// ONE WARP PER NODE (R8 proven structure). Half-warp edge parallelism:
// row=256B=16 lanes x uint4; halves merged via shfl_xor(16); full-warp epilogue,
// lane owns group 2*li+h. hb pre-scaled by dis:
//   result = dv*(sum_s hb[s] + hb[v]) + bias
// mode 0: relu (layer 0); mode 1: +residual, relu; mode 2: +residual, fused pool
__global__ __launch_bounds__(256) void agg_kernel(const float* __restrict__ b,
                                                  const float* __restrict__ gamma,
                                                  const float* __restrict__ beta,
                                                  const void* __restrict__ batch,
                                                  int mode) {
    int warp = (blockIdx.x * blockDim.x + threadIdx.x) >> 5;
    int lane = threadIdx.x & 31;
    if (warp >= N_NODES) return;
    int v = warp;
    int h  = lane >> 4;     // half-warp id
    int li = lane & 15;     // lane within half

    const uint4* hb4 = (const uint4*)g_hb;   // 16 uint4 per row

    int beg = g_rowptr[v];
    int end = g_rowptr[v + 1];

    float acc[8];
#pragma unroll
    for (int q = 0; q < 8; ++q) acc[q] = 0.f;

    int e = beg;
    for (; e + 8 <= end; e += 8) {
        int ib = e + h * 4;
        int s0 = __ldg(&g_esrc[ib]);
        int s1 = __ldg(&g_esrc[ib + 1]);
        int s2 = __ldg(&g_esrc[ib + 2]);
        int s3 = __ldg(&g_esrc[ib + 3]);
        uint4 u0 = hb4[(size_t)s0 * 16 + li];
        uint4 u1 = hb4[(size_t)s1 * 16 + li];
        uint4 u2 = hb4[(size_t)s2 * 16 + li];
        uint4 u3 = hb4[(size_t)s3 * 16 + li];
        acc8(acc, u0);
        acc8(acc, u1);
        acc8(acc, u2);
        acc8(acc, u3);
    }
    for (; e + 2 <= end; e += 2) {
        int s = __ldg(&g_esrc[e + h]);
        uint4 u = hb4[(size_t)s * 16 + li];
        acc8(acc, u);
    }
    if (e < end && h == 0) {
        int s = __ldg(&g_esrc[e]);
        uint4 u = hb4[(size_t)s * 16 + li];
        acc8(acc, u);
    }

    // merge halves: all 32 lanes now hold full sums for segment li
#pragma unroll
    for (int q = 0; q < 8; ++q)
        acc[q] += __shfl_xor_sync(0xffffffffu, acc[q], 16);

    int gidx = 2 * li + h;          // uint2/float4 group index this lane owns
    float r0v = acc[4 * h],     r1v = acc[4 * h + 1];
    float r2v = acc[4 * h + 2], r3v = acc[4 * h + 3];

    // self loop (hb[v] already = h*dv)
    {
        uint2 us = ((const uint2*)(g_hb + (size_t)v * D))[gidx];
        float2 f0 = __bfloat1622float2(*(__nv_bfloat162*)&us.x);
        float2 f1 = __bfloat1622float2(*(__nv_bfloat162*)&us.y);
        r0v += f0.x; r1v += f0.y; r2v += f1.x; r3v += f1.y;
    }
    float dv = g_dis[v];
    float4 bb = ((const float4*)b)[gidx];
    r0v = fmaf(r0v, dv, bb.x); r1v = fmaf(r1v, dv, bb.y);
    r2v = fmaf(r2v, dv, bb.z); r3v = fmaf(r3v, dv, bb.w);

    // LayerNorm across 128: full-warp reduce
    float s1v = r0v + r1v + r2v + r3v;
    float s2v = r0v * r0v + r1v * r1v + r2v * r2v + r3v * r3v;
#pragma unroll
    for (int off = 16; off > 0; off >>= 1) {
        s1v += __shfl_xor_sync(0xffffffffu, s1v, off);
        s2v += __shfl_xor_sync(0xffffffffu, s2v, off);
    }
    float mu = s1v * (1.0f / 128.0f);
    float var = fmaf(s2v, 1.0f / 128.0f, -mu * mu);
    float inv = rsqrtf(var + LN_EPS);

    float4 g4 = ((const float4*)gamma)[gidx];
    float4 be4 = ((const float4*)beta)[gidx];
    r0v = fmaf((r0v - mu) * inv, g4.x, be4.x);
    r1v = fmaf((r1v - mu) * inv, g4.y, be4.y);
    r2v = fmaf((r2v - mu) * inv, g4.z, be4.z);
    r3v = fmaf((r3v - mu) * inv, g4.w, be4.w);

    if (mode >= 1) {
        uint2 c = ((const uint2*)(g_curb + (size_t)v * D))[gidx];
        float2 f0 = __bfloat1622float2(*(__nv_bfloat162*)&c.x);
        float2 f1 = __bfloat1622float2(*(__nv_bfloat162*)&c.y);
        r0v += f0.x; r1v += f0.y; r2v += f1.x; r3v += f1.y;
    }
    if (mode != 2) {
        r0v = fmaxf(r0v, 0.f); r1v = fmaxf(r1v, 0.f);
        r2v = fmaxf(r2v, 0.f); r3v = fmaxf(r3v, 0.f);
        uint2 o;
        __nv_bfloat162 p0 = __floats2bfloat162_rn(r0v, r1v);
        __nv_bfloat162 p1 = __floats2bfloat162_rn(r2v, r3v);
        o.x = *(uint32_t*)&p0; o.y = *(uint32_t*)&p1;
        ((uint2*)(g_curb + (size_t)v * D))[gidx] = o;
    } else {
        int g = load_idx(batch, v, g_is64_b);
        float* dst = &g_pool[(size_t)g * D + gidx * 4];
        asm volatile("red.global.add.v4.f32 [%0], {%1, %2, %3, %4};"
                     :: "l"(dst), "f"(r0v), "f"(r1v), "f"(r2v), "f"(r3v)
                     : "memory");
        if (lane == 0) atomicAdd(&g_pcnt[g], 1.0f);
    }
}

// ---------------- 9. final linear ----------------
__global__ void final_kernel(const float* __restrict__ lin_w,
                             const float* __restrict__ lin_b,
                             float* __restrict__ out) {
    int g = blockIdx.x;
    int t = threadIdx.x;   // 128 threads
    float cnt = g_pcnt[g];
    float invc = 1.0f / fmaxf(cnt, 1.0f);
    float val = g_pool[(size_t)g * D + t] * invc * lin_w[t];
#pragma unroll
    for (int off = 16; off > 0; off >>= 1)
        val += __shfl_xor_sync(0xffffffffu, val, off);
    __shared__ float ws[4];
    if ((t & 31) == 0) ws[t >> 5] = val;
    __syncthreads();
    if (t == 0) out[g] = ws[0] + ws[1] + ws[2] + ws[3] + lin_b[0];
}

// ---------------- launch ----------------
extern "C" void kernel_launch(void* const* d_in, const int* in_sizes, int n_in,
                              void* d_out, int out_size) {
    const void* x = 0; const void* ei = 0; const void* batch = 0;
    const void* Ws = 0; const void* lin_w = 0; const void* lin_b = 0;
    const void* small512[3] = {0, 0, 0};
    int n512 = 0;
    for (int i = 0; i < n_in; ++i) {
        switch (in_sizes[i]) {
            case N_NODES * D:      x = d_in[i]; break;
            case 2 * N_EDGES:      ei = d_in[i]; break;
            case N_NODES:          batch = d_in[i]; break;
            case N_LAYERS * D * D: Ws = d_in[i]; break;
            case D:                lin_w = d_in[i]; break;
            case 1:                lin_b = d_in[i]; break;
            case N_LAYERS * D:     if (n512 < 3) small512[n512++] = d_in[i]; break;
            default: break;
        }
    }
    const float* xf      = (const float*)x;
    const float* Wsf     = (const float*)Ws;
    const float* bsf     = (const float*)small512[0];
    const float* gammasf = (const float*)small512[1];
    const float* betasf  = (const float*)small512[2];
    const float* lin_wf  = (const float*)lin_w;
    const float* lin_bf  = (const float*)lin_b;
    float* out = (float*)d_out;

    __nv_bfloat16* hb_ptr; cudaGetSymbolAddress((void**)&hb_ptr, g_hb);

    prep_all_kernel<<<NB_SCAN, 256>>>(ei, (const int*)ei, (const int*)batch);

    int ggrid = (N_NODES + 127) / 128;
    int agrid = (N_NODES * 32 + 255) / 256;
    for (int l = 0; l < N_LAYERS; ++l) {
        gemm_tc_kernel<<<ggrid, 256>>>(xf, (l == 0) ? 1 : 0,
                                       Wsf + (size_t)l * D * D, hb_ptr);
        int mode = (l == 0) ? 0 : (l == N_LAYERS - 1 ? 2 : 1);
        agg_kernel<<<agrid, 256>>>(bsf + (size_t)l * D, gammasf + (size_t)l * D,
                                   betasf + (size_t)l * D, batch, mode);
    }

    final_kernel<<<N_GRAPHS, 128>>>(lin_wf, lin_bf, out);
}

// round 16
// speedup vs baseline: 1.0242x; 1.0242x over previous
#include <cuda_runtime.h>
#include <cuda_bf16.h>
#include <math.h>
#include <stdint.h>

#define N_NODES 100000
#define N_EDGES 1600000
#define D 128
#define N_LAYERS 4
#define N_GRAPHS 512
#define LN_EPS 1e-5f
#define NB_SCAN 391   // ceil(N_NODES/256)

// ---------------- scratch (device globals; no allocation allowed) ----------------
__device__ __align__(16) __nv_bfloat16 g_hb[N_NODES * D];   // post-GEMM feats, bf16, pre-scaled by dis
__device__ __align__(16) __nv_bfloat16 g_curb[N_NODES * D]; // layer features (bf16)
__device__ int   g_rowptr[N_NODES + 1];
__device__ int   g_cnt[N_NODES];          // in-degree, then CSR fill cursor
__device__ int   g_esrc[N_EDGES];         // edge sources grouped by dst
__device__ __align__(16) float g_dis[N_NODES];        // deg^{-1/2} (with self loop)
__device__ __align__(16) float g_pool[N_GRAPHS * D];
__device__ __align__(16) float g_pcnt[N_GRAPHS];
__device__ int g_bsum[NB_SCAN];
__device__ int g_boff[NB_SCAN];
__device__ int g_is64_ei;
__device__ int g_is64_b;

// ---------------- helpers ----------------
__device__ __forceinline__ int load_idx(const void* p, long long i, int is64) {
    return is64 ? (int)((const long long*)p)[i] : ((const int*)p)[i];
}

__device__ __forceinline__ uint32_t to_tf32(float f) {
    uint32_t u;
    asm("cvt.rna.tf32.f32 %0, %1;" : "=r"(u) : "f"(f));
    return u;
}

__device__ __forceinline__ void mma_tf32(float* c, const uint32_t* a, const uint32_t* b) {
    asm volatile(
        "mma.sync.aligned.m16n8k8.row.col.f32.tf32.tf32.f32 "
        "{%0,%1,%2,%3}, {%4,%5,%6,%7}, {%8,%9}, {%0,%1,%2,%3};"
        : "+f"(c[0]), "+f"(c[1]), "+f"(c[2]), "+f"(c[3])
        : "r"(a[0]), "r"(a[1]), "r"(a[2]), "r"(a[3]), "r"(b[0]), "r"(b[1]));
}

__device__ __forceinline__ void acc8(float* acc, uint4 u) {
    float2 f0 = __bfloat1622float2(*(__nv_bfloat162*)&u.x);
    float2 f1 = __bfloat1622float2(*(__nv_bfloat162*)&u.y);
    float2 f2 = __bfloat1622float2(*(__nv_bfloat162*)&u.z);
    float2 f3 = __bfloat1622float2(*(__nv_bfloat162*)&u.w);
    acc[0] += f0.x; acc[1] += f0.y; acc[2] += f1.x; acc[3] += f1.y;
    acc[4] += f2.x; acc[5] += f2.y; acc[6] += f3.x; acc[7] += f3.y;
}

// ---------------- 1. zero counters + dtype detect (block 0) ----------------
__global__ void zero_detect_kernel(const int* __restrict__ ei32, int n_e,
                                   const int* __restrict__ b32,  int n_b) {
    int i = blockIdx.x * blockDim.x + threadIdx.x;
    if (i < N_NODES) g_cnt[i] = 0;
    if (i < N_GRAPHS * D) g_pool[i] = 0.f;
    if (i < N_GRAPHS) g_pcnt[i] = 0.f;
    if (blockIdx.x == 0) {
        __shared__ int cnt_e, cnt_b;
        if (threadIdx.x == 0) { cnt_e = 0; cnt_b = 0; }
        __syncthreads();
        for (int k = threadIdx.x; k < 256; k += blockDim.x) {
            long long pe = (long long)(2 * k + 1) * n_e / 512;
            pe |= 1; if (pe >= n_e) pe = (n_e - 1) | 1;
            if (pe < n_e && ei32[pe] != 0) atomicAdd(&cnt_e, 1);
            long long pb = (long long)(2 * k + 1) * n_b / 512;
            pb |= 1; if (pb >= n_b) pb = (n_b - 1) | 1;
            if (pb < n_b && b32[pb] != 0) atomicAdd(&cnt_b, 1);
        }
        __syncthreads();
        if (threadIdx.x == 0) {
            g_is64_ei = (cnt_e == 0) ? 1 : 0;
            g_is64_b  = (cnt_b == 0) ? 1 : 0;
        }
    }
}

// ---------------- 2. in-degree histogram ----------------
__global__ void hist_kernel(const void* __restrict__ ei) {
    int i = blockIdx.x * blockDim.x + threadIdx.x;
    if (i >= N_EDGES) return;
    int dst = load_idx(ei, (long long)N_EDGES + i, g_is64_ei);
    atomicAdd(&g_cnt[dst], 1);
}

// ---------------- 3a. per-block reduce of g_cnt ----------------
__global__ __launch_bounds__(256) void scan_reduce_kernel() {
    int t = threadIdx.x, b = blockIdx.x;
    int i = b * 256 + t;
    int v = (i < N_NODES) ? g_cnt[i] : 0;
    int s = v;
#pragma unroll
    for (int off = 16; off > 0; off >>= 1) s += __shfl_xor_sync(0xffffffffu, s, off);
    __shared__ int ws[8];
    if ((t & 31) == 0) ws[t >> 5] = s;
    __syncthreads();
    if (t == 0) {
        int tot = 0;
#pragma unroll
        for (int w = 0; w < 8; ++w) tot += ws[w];
        g_bsum[b] = tot;
    }
}

// ---------------- 3b. scan block sums (single block, shfl-based) ----------------
__global__ __launch_bounds__(512) void scan_bsum_kernel() {
    int t = threadIdx.x, lane = t & 31, wid = t >> 5;   // 16 warps
    int v = (t < NB_SCAN) ? g_bsum[t] : 0;
    int incl = v;
#pragma unroll
    for (int off = 1; off < 32; off <<= 1) {
        int n = __shfl_up_sync(0xffffffffu, incl, off);
        if (lane >= off) incl += n;
    }
    __shared__ int wsum[16], woff[16];
    if (lane == 31) wsum[wid] = incl;
    __syncthreads();
    if (wid == 0 && lane < 16) {
        int wv = wsum[lane];
        int wi = wv;
#pragma unroll
        for (int off = 1; off < 16; off <<= 1) {
            int n = __shfl_up_sync(0xffffu, wi, off);
            if (lane >= off) wi += n;
        }
        woff[lane] = wi - wv;
        if (lane == 15) g_rowptr[N_NODES] = wi;
    }
    __syncthreads();
    if (t < NB_SCAN) g_boff[t] = woff[wid] + (incl - v);
}

// ---------------- 3c. per-block scan + rowptr/cursor/dis (prep fused) -----------
__global__ __launch_bounds__(256) void scan_block_kernel() {
    int t = threadIdx.x, b = blockIdx.x;
    int lane = t & 31, wid = t >> 5;
    int i = b * 256 + t;
    int v = (i < N_NODES) ? g_cnt[i] : 0;
    int incl = v;
#pragma unroll
    for (int off = 1; off < 32; off <<= 1) {
        int n = __shfl_up_sync(0xffffffffu, incl, off);
        if (lane >= off) incl += n;
    }
    __shared__ int wsum[8], woff[8];
    if (lane == 31) wsum[wid] = incl;
    __syncthreads();
    if (wid == 0 && lane < 8) {
        int wv = wsum[lane];
        int wi = wv;
#pragma unroll
        for (int off = 1; off < 8; off <<= 1) {
            int n = __shfl_up_sync(0xffu, wi, off);
            if (lane >= off) wi += n;
        }
        woff[lane] = wi - wv;
    }
    __syncthreads();
    if (i < N_NODES) {
        int rp = g_boff[b] + woff[wid] + (incl - v);
        g_rowptr[i] = rp;
        g_cnt[i] = rp;                          // CSR fill cursor
        g_dis[i] = rsqrtf((float)v + 1.0f);     // deg^{-1/2} with self loop
    }
}

// ---------------- 5. CSR fill ----------------
__global__ void fill_kernel(const void* __restrict__ ei) {
    int i = blockIdx.x * blockDim.x + threadIdx.x;
    if (i >= N_EDGES) return;
    int is64 = g_is64_ei;
    int src = load_idx(ei, i, is64);
    int dst = load_idx(ei, (long long)N_EDGES + i, is64);
    int pos = atomicAdd(&g_cnt[dst], 1);
    g_esrc[pos] = src;
}

// ---------------- 6. TF32 GEMM (R8 structure + k-pair packed LDS.64 fragments) ---
// outb[v, :] = bf16( (A @ W)[v, :] * dis[v] )
// Packed layouts (words):
//   sX: row r, kk-group g: 8 words [k0,k4,k1,k5,k2,k6,k3,k7]; addr r*40 + g*8
//       -> uint2 at r*40 + g*8 + tc*2 = (A[r][k=g*8+tc], A[r][k=g*8+tc+4])
//   sW: pair-row pr = kk*4 + tc (k = kc*32+kk*8+tc); addr pr*264 + n*2
//       -> uint2 = (W[k][n], W[k+4][n])
// Both fragment-load patterns verified bank-conflict-free per half-warp.
__global__ __launch_bounds__(256) void gemm_tc_kernel(const float* __restrict__ Af,
                                                      int a_f32,
                                                      const float* __restrict__ W,
                                                      __nv_bfloat16* __restrict__ outb) {
    __shared__ uint32_t sX[128 * 40];   // 20 KB
    __shared__ uint32_t sW[16 * 264];   // 16.5 KB
    int tid = threadIdx.x;
    int lane = tid & 31, wid = tid >> 5;
    int warp_m = wid >> 1, warp_n = wid & 1;
    int tg = lane >> 2, tc = lane & 3;
    int br = blockIdx.x * 128;

    float acc[2][8][4];
#pragma unroll
    for (int mt = 0; mt < 2; ++mt)
#pragma unroll
        for (int nt = 0; nt < 8; ++nt)
#pragma unroll
            for (int q = 0; q < 4; ++q) acc[mt][nt][q] = 0.f;

    for (int kc = 0; kc < 4; ++kc) {
        // ---- load A chunk (128 rows x 32 k), packed pairs ----
#pragma unroll
        for (int it = 0; it < 2; ++it) {
            int task = tid + it * 256;      // 512 tasks: row x 4 chunks of 8k
            int row = task >> 2, ck = task & 3;
            uint32_t* dst = &sX[row * 40 + ck * 8];
            if (a_f32) {
                float4 v0 = make_float4(0.f, 0.f, 0.f, 0.f);
                float4 v1 = make_float4(0.f, 0.f, 0.f, 0.f);
                if (br + row < N_NODES) {
                    const float* base = &Af[(size_t)(br + row) * D + kc * 32 + ck * 8];
                    v0 = *(const float4*)&base[0];
                    v1 = *(const float4*)&base[4];
                }
                *(uint4*)&dst[0] = make_uint4(to_tf32(v0.x), to_tf32(v1.x),
                                              to_tf32(v0.y), to_tf32(v1.y));
                *(uint4*)&dst[4] = make_uint4(to_tf32(v0.z), to_tf32(v1.z),
                                              to_tf32(v0.w), to_tf32(v1.w));
            } else {
                uint4 u = make_uint4(0, 0, 0, 0);
                if (br + row < N_NODES)
                    u = *(const uint4*)&g_curb[(size_t)(br + row) * D + kc * 32 + ck * 8];
                // u = 8 bf16: x=(k0,k1) y=(k2,k3) z=(k4,k5) w=(k6,k7)
                *(uint4*)&dst[0] = make_uint4(u.x << 16, u.z << 16,
                                              u.x & 0xffff0000u, u.z & 0xffff0000u);
                *(uint4*)&dst[4] = make_uint4(u.y << 16, u.w << 16,
                                              u.y & 0xffff0000u, u.w & 0xffff0000u);
            }
        }
        // ---- load W chunk (32 k x 128 n), packed pairs ----
#pragma unroll
        for (int it = 0; it < 2; ++it) {
            int task = tid + it * 256;      // 512 tasks: 16 pair-rows x 32 col-chunks
            int pr = task >> 5;             // 0..15 = kk*4 + tcl
            int q = task & 31;
            int kk = pr >> 2, tcl = pr & 3;
            int k = kc * 32 + kk * 8 + tcl;
            float4 w0 = *(const float4*)&W[(size_t)k * D + q * 4];
            float4 w1 = *(const float4*)&W[(size_t)(k + 4) * D + q * 4];
            uint32_t* dst = &sW[pr * 264 + q * 8];
            *(uint4*)&dst[0] = make_uint4(to_tf32(w0.x), to_tf32(w1.x),
                                          to_tf32(w0.y), to_tf32(w1.y));
            *(uint4*)&dst[4] = make_uint4(to_tf32(w0.z), to_tf32(w1.z),
                                          to_tf32(w0.w), to_tf32(w1.w));
        }
        __syncthreads();

#pragma unroll
        for (int kk = 0; kk < 4; ++kk) {
            uint32_t a[2][4], b[8][2];
#pragma unroll
            for (int mt = 0; mt < 2; ++mt) {
                int r0 = warp_m * 32 + mt * 16 + tg;
                uint2 pa = *(uint2*)&sX[r0 * 40 + kk * 8 + tc * 2];
                uint2 pb = *(uint2*)&sX[(r0 + 8) * 40 + kk * 8 + tc * 2];
                a[mt][0] = pa.x; a[mt][1] = pb.x;
                a[mt][2] = pa.y; a[mt][3] = pb.y;
            }
            int pr = kk * 4 + tc;
#pragma unroll
            for (int nt = 0; nt < 8; ++nt) {
                int n0 = warp_n * 64 + nt * 8 + tg;
                uint2 pw = *(uint2*)&sW[pr * 264 + n0 * 2];
                b[nt][0] = pw.x; b[nt][1] = pw.y;
            }
#pragma unroll
            for (int mt = 0; mt < 2; ++mt)
#pragma unroll
                for (int nt = 0; nt < 8; ++nt)
                    mma_tf32(acc[mt][nt], a[mt], b[nt]);
        }
        __syncthreads();
    }

#pragma unroll
    for (int mt = 0; mt < 2; ++mt) {
        int r0 = br + warp_m * 32 + mt * 16 + tg;
        float ds0 = (r0 < N_NODES) ? g_dis[r0] : 0.f;
        float ds1 = (r0 + 8 < N_NODES) ? g_dis[r0 + 8] : 0.f;
#pragma unroll
        for (int nt = 0; nt < 8; ++nt) {
            int c0 = warp_n * 64 + nt * 8 + 2 * tc;
            if (r0 < N_NODES) {
                __nv_bfloat162 p = __floats2bfloat162_rn(acc[mt][nt][0] * ds0,
                                                         acc[mt][nt][1] * ds0);
                *(__nv_bfloat162*)&outb[(size_t)r0 * D + c0] = p;
            }
            if (r0 + 8 < N_NODES) {
                __nv_bfloat162 p = __floats2bfloat162_rn(acc[mt][nt][2] * ds1,
                                                         acc[mt][nt][3] * ds1);
                *(__nv_bfloat162*)&outb[(size_t)(r0 + 8) * D + c0] = p;
            }
        }
    }
}

// ---------------- 7. fused aggregation + bias + LN + residual/relu (+pool) -------
// ONE WARP PER NODE (R8 proven structure). Half-warp edge parallelism:
// row=256B=16 lanes x uint4; halves merged via shfl_xor(16); full-warp epilogue,
// lane owns group 2*li+h. hb pre-scaled by dis:
//   result = dv*(sum_s hb[s] + hb[v]) + bias
// mode 0: relu (layer 0); mode 1: +residual, relu; mode 2: +residual, fused pool
__global__ __launch_bounds__(256) void agg_kernel(const float* __restrict__ b,
                                                  const float* __restrict__ gamma,
                                                  const float* __restrict__ beta,
                                                  const void* __restrict__ batch,
                                                  int mode) {
    int warp = (blockIdx.x * blockDim.x + threadIdx.x) >> 5;
    int lane = threadIdx.x & 31;
    if (warp >= N_NODES) return;
    int v = warp;
    int h  = lane >> 4;     // half-warp id
    int li = lane & 15;     // lane within half

    const uint4* hb4 = (const uint4*)g_hb;   // 16 uint4 per row

    int beg = g_rowptr[v];
    int end = g_rowptr[v + 1];

    float acc[8];
#pragma unroll
    for (int q = 0; q < 8; ++q) acc[q] = 0.f;

    int e = beg;
    for (; e + 8 <= end; e += 8) {
        int ib = e + h * 4;
        int s0 = __ldg(&g_esrc[ib]);
        int s1 = __ldg(&g_esrc[ib + 1]);
        int s2 = __ldg(&g_esrc[ib + 2]);
        int s3 = __ldg(&g_esrc[ib + 3]);
        uint4 u0 = hb4[(size_t)s0 * 16 + li];
        uint4 u1 = hb4[(size_t)s1 * 16 + li];
        uint4 u2 = hb4[(size_t)s2 * 16 + li];
        uint4 u3 = hb4[(size_t)s3 * 16 + li];
        acc8(acc, u0);
        acc8(acc, u1);
        acc8(acc, u2);
        acc8(acc, u3);
    }
    for (; e + 2 <= end; e += 2) {
        int s = __ldg(&g_esrc[e + h]);
        uint4 u = hb4[(size_t)s * 16 + li];
        acc8(acc, u);
    }
    if (e < end && h == 0) {
        int s = __ldg(&g_esrc[e]);
        uint4 u = hb4[(size_t)s * 16 + li];
        acc8(acc, u);
    }

    // merge halves: all 32 lanes now hold full sums for segment li
#pragma unroll
    for (int q = 0; q < 8; ++q)
        acc[q] += __shfl_xor_sync(0xffffffffu, acc[q], 16);

    int gidx = 2 * li + h;          // uint2/float4 group index this lane owns
    float r0v = acc[4 * h],     r1v = acc[4 * h + 1];
    float r2v = acc[4 * h + 2], r3v = acc[4 * h + 3];

    // self loop (hb[v] already = h*dv)
    {
        uint2 us = ((const uint2*)(g_hb + (size_t)v * D))[gidx];
        float2 f0 = __bfloat1622float2(*(__nv_bfloat162*)&us.x);
        float2 f1 = __bfloat1622float2(*(__nv_bfloat162*)&us.y);
        r0v += f0.x; r1v += f0.y; r2v += f1.x; r3v += f1.y;
    }
    float dv = g_dis[v];
    float4 bb = ((const float4*)b)[gidx];
    r0v = fmaf(r0v, dv, bb.x); r1v = fmaf(r1v, dv, bb.y);
    r2v = fmaf(r2v, dv, bb.z); r3v = fmaf(r3v, dv, bb.w);

    // LayerNorm across 128: full-warp reduce
    float s1v = r0v + r1v + r2v + r3v;
    float s2v = r0v * r0v + r1v * r1v + r2v * r2v + r3v * r3v;
#pragma unroll
    for (int off = 16; off > 0; off >>= 1) {
        s1v += __shfl_xor_sync(0xffffffffu, s1v, off);
        s2v += __shfl_xor_sync(0xffffffffu, s2v, off);
    }
    float mu = s1v * (1.0f / 128.0f);
    float var = fmaf(s2v, 1.0f / 128.0f, -mu * mu);
    float inv = rsqrtf(var + LN_EPS);

    float4 g4 = ((const float4*)gamma)[gidx];
    float4 be4 = ((const float4*)beta)[gidx];
    r0v = fmaf((r0v - mu) * inv, g4.x, be4.x);
    r1v = fmaf((r1v - mu) * inv, g4.y, be4.y);
    r2v = fmaf((r2v - mu) * inv, g4.z, be4.z);
    r3v = fmaf((r3v - mu) * inv, g4.w, be4.w);

    if (mode >= 1) {
        uint2 c = ((const uint2*)(g_curb + (size_t)v * D))[gidx];
        float2 f0 = __bfloat1622float2(*(__nv_bfloat162*)&c.x);
        float2 f1 = __bfloat1622float2(*(__nv_bfloat162*)&c.y);
        r0v += f0.x; r1v += f0.y; r2v += f1.x; r3v += f1.y;
    }
    if (mode != 2) {
        r0v = fmaxf(r0v, 0.f); r1v = fmaxf(r1v, 0.f);
        r2v = fmaxf(r2v, 0.f); r3v = fmaxf(r3v, 0.f);
        uint2 o;
        __nv_bfloat162 p0 = __floats2bfloat162_rn(r0v, r1v);
        __nv_bfloat162 p1 = __floats2bfloat162_rn(r2v, r3v);
        o.x = *(uint32_t*)&p0; o.y = *(uint32_t*)&p1;
        ((uint2*)(g_curb + (size_t)v * D))[gidx] = o;
    } else {
        int g = load_idx(batch, v, g_is64_b);
        float* dst = &g_pool[(size_t)g * D + gidx * 4];
        asm volatile("red.global.add.v4.f32 [%0], {%1, %2, %3, %4};"
                     :: "l"(dst), "f"(r0v), "f"(r1v), "f"(r2v), "f"(r3v)
                     : "memory");
        if (lane == 0) atomicAdd(&g_pcnt[g], 1.0f);
    }
}

// ---------------- 9. final linear ----------------
__global__ void final_kernel(const float* __restrict__ lin_w,
                             const float* __restrict__ lin_b,
                             float* __restrict__ out) {
    int g = blockIdx.x;
    int t = threadIdx.x;   // 128 threads
    float cnt = g_pcnt[g];
    float invc = 1.0f / fmaxf(cnt, 1.0f);
    float val = g_pool[(size_t)g * D + t] * invc * lin_w[t];
#pragma unroll
    for (int off = 16; off > 0; off >>= 1)
        val += __shfl_xor_sync(0xffffffffu, val, off);
    __shared__ float ws[4];
    if ((t & 31) == 0) ws[t >> 5] = val;
    __syncthreads();
    if (t == 0) out[g] = ws[0] + ws[1] + ws[2] + ws[3] + lin_b[0];
}

// ---------------- launch ----------------
extern "C" void kernel_launch(void* const* d_in, const int* in_sizes, int n_in,
                              void* d_out, int out_size) {
    const void* x = 0; const void* ei = 0; const void* batch = 0;
    const void* Ws = 0; const void* lin_w = 0; const void* lin_b = 0;
    const void* small512[3] = {0, 0, 0};
    int n512 = 0;
    for (int i = 0; i < n_in; ++i) {
        switch (in_sizes[i]) {
            case N_NODES * D:      x = d_in[i]; break;
            case 2 * N_EDGES:      ei = d_in[i]; break;
            case N_NODES:          batch = d_in[i]; break;
            case N_LAYERS * D * D: Ws = d_in[i]; break;
            case D:                lin_w = d_in[i]; break;
            case 1:                lin_b = d_in[i]; break;
            case N_LAYERS * D:     if (n512 < 3) small512[n512++] = d_in[i]; break;
            default: break;
        }
    }
    const float* xf      = (const float*)x;
    const float* Wsf     = (const float*)Ws;
    const float* bsf     = (const float*)small512[0];
    const float* gammasf = (const float*)small512[1];
    const float* betasf  = (const float*)small512[2];
    const float* lin_wf  = (const float*)lin_w;
    const float* lin_bf  = (const float*)lin_b;
    float* out = (float*)d_out;

    __nv_bfloat16* hb_ptr; cudaGetSymbolAddress((void**)&hb_ptr, g_hb);

    int zgrid = (N_NODES + 255) / 256;
    if ((N_GRAPHS * D + 255) / 256 > zgrid) zgrid = (N_GRAPHS * D + 255) / 256;
    zero_detect_kernel<<<zgrid, 256>>>((const int*)ei, 2 * N_EDGES,
                                       (const int*)batch, N_NODES);
    hist_kernel<<<(N_EDGES + 255) / 256, 256>>>(ei);
    scan_reduce_kernel<<<NB_SCAN, 256>>>();
    scan_bsum_kernel<<<1, 512>>>();
    scan_block_kernel<<<NB_SCAN, 256>>>();   // rowptr + cursor + dis (prep fused)
    fill_kernel<<<(N_EDGES + 255) / 256, 256>>>(ei);

    int ggrid = (N_NODES + 127) / 128;
    int agrid = (N_NODES * 32 + 255) / 256;
    for (int l = 0; l < N_LAYERS; ++l) {
        gemm_tc_kernel<<<ggrid, 256>>>(xf, (l == 0) ? 1 : 0,
                                       Wsf + (size_t)l * D * D, hb_ptr);
        int mode = (l == 0) ? 0 : (l == N_LAYERS - 1 ? 2 : 1);
        agg_kernel<<<agrid, 256>>>(bsf + (size_t)l * D, gammasf + (size_t)l * D,
                                   betasf + (size_t)l * D, batch, mode);
    }

    final_kernel<<<N_GRAPHS, 128>>>(lin_wf, lin_bf, out);
}